// round 16
// baseline (speedup 1.0000x reference)
#include <cuda_runtime.h>
#include <cuda_bf16.h>
#include <cstdint>
#include <math.h>

// Problem constants
#define BB   64
#define TT   256
#define DD   512
#define HH   1024
#define GG   4096   // 4*H
#define NCTA2 128   // persistent recurrent kernel grid size

// ---------------- device scratch (static; no cudaMalloc allowed) --------------
__device__ float    g_gates[(size_t)TT * BB * GG];          // x@W_ih^T + biases
__device__ __align__(16) unsigned g_xh[(size_t)TT * BB * (DD/2)];  // X hi plane (u32 = 2 bf16)
__device__ __align__(16) unsigned g_xl[(size_t)TT * BB * (DD/2)];  // X lo plane
__device__ __align__(16) unsigned g_wih_h[GG * (DD/2)];     // W_ih hi plane
__device__ __align__(16) unsigned g_wih_l[GG * (DD/2)];     // W_ih lo plane
__device__ __align__(16) __nv_bfloat16 g_hh[2][BB * HH];    // h hi, double buffered
__device__ __align__(16) __nv_bfloat16 g_hl[2][BB * HH];    // h lo
__device__ float    g_hout[BB * HH];                        // last-active h (fp32)
__device__ int      g_perm[BB];
__device__ int      g_act[TT];
__device__ int      g_is64;
__device__ unsigned g_cnt8[8 * 64];                         // sub-counters, 256B apart
__device__ unsigned g_cnt = 0;                              // master counter
__device__ unsigned g_gen = 0;                              // barrier generation

// ---------------- small asm helpers --------------------------------------------
__device__ __forceinline__ void cp16(unsigned saddr, const void* g) {
    asm volatile("cp.async.cg.shared.global [%0], [%1], 16;"
                 :: "r"(saddr), "l"(g) : "memory");
}
__device__ __forceinline__ void cp_commit() {
    asm volatile("cp.async.commit_group;" ::: "memory");
}
template<int N> __device__ __forceinline__ void cp_wait() {
    asm volatile("cp.async.wait_group %0;" :: "n"(N) : "memory");
}
__device__ __forceinline__ uint4 ldcg4(const unsigned* p) {
    uint4 v;
    asm volatile("ld.global.cg.v4.u32 {%0,%1,%2,%3}, [%4];"
                 : "=r"(v.x), "=r"(v.y), "=r"(v.z), "=r"(v.w) : "l"(p) : "memory");
    return v;
}
__device__ __forceinline__ void ldsm4(unsigned* r, const __nv_bfloat16* p) {
    unsigned a = (unsigned)__cvta_generic_to_shared((void*)p);
    asm volatile("ldmatrix.sync.aligned.m8n8.x4.shared.b16 {%0,%1,%2,%3}, [%4];"
                 : "=r"(r[0]), "=r"(r[1]), "=r"(r[2]), "=r"(r[3]) : "r"(a));
}
__device__ __forceinline__ void mma16816(float* c, const unsigned* a,
                                         unsigned b0, unsigned b1) {
    asm volatile("mma.sync.aligned.m16n8k16.row.col.f32.bf16.bf16.f32 "
                 "{%0,%1,%2,%3},{%4,%5,%6,%7},{%8,%9},{%0,%1,%2,%3};"
                 : "+f"(c[0]), "+f"(c[1]), "+f"(c[2]), "+f"(c[3])
                 : "r"(a[0]), "r"(a[1]), "r"(a[2]), "r"(a[3]), "r"(b0), "r"(b1));
}

// ---------------- bf16 hi/lo split + pack --------------------------------------
__device__ __forceinline__ unsigned packbf(__nv_bfloat16 a, __nv_bfloat16 b) {
    return ((unsigned)__bfloat16_as_ushort(b) << 16) | (unsigned)__bfloat16_as_ushort(a);
}
__device__ __forceinline__ void split_pack(float x, float y, unsigned& hi, unsigned& lo) {
    __nv_bfloat16 hx = __float2bfloat16(x);
    __nv_bfloat16 hy = __float2bfloat16(y);
    hi = packbf(hx, hy);
    lo = packbf(__float2bfloat16(x - __bfloat162float(hx)),
                __float2bfloat16(y - __bfloat162float(hy)));
}

// ---------------- grid barrier (monotone generation, TREE counters) ------------
__device__ __forceinline__ void grid_barrier(unsigned& gen)
{
    __syncthreads();
    gen++;
    if (threadIdx.x == 0) {
        __threadfence();
        int grp = blockIdx.x & 7;
        unsigned prev = atomicAdd(&g_cnt8[grp * 64], 1u);
        bool released = false;
        if (prev == 15u) {                       // last of this 16-CTA group
            atomicExch(&g_cnt8[grp * 64], 0u);   // reset before master arrive
            unsigned p2 = atomicAdd(&g_cnt, 1u);
            if (p2 == 7u) {                      // last group
                atomicExch(&g_cnt, 0u);
                __threadfence();
                atomicExch(&g_gen, gen);
                released = true;
            }
        }
        if (!released) {
            while (*((volatile unsigned*)&g_gen) < gen) { }
            __threadfence();
        }
    }
    __syncthreads();
}

// ---------------- prep: parallel rank sort by length (desc, stable) ------------
__global__ void k_prep(const int* __restrict__ len32)
{
    __shared__ int slen[BB];
    const int tid = threadIdx.x;
    const int is64 = (len32[1] == 0) ? 1 : 0;   // lengths >= 1 always
    if (tid == 0) g_is64 = is64;
    if (tid < BB) slen[tid] = is64 ? len32[2 * tid] : len32[tid];
    __syncthreads();
    if (tid < BB) {
        int li = slen[tid], r = 0;
        for (int j = 0; j < BB; j++) {
            int lj = slen[j];
            r += (lj > li) || (lj == li && j < tid);
        }
        g_perm[r] = tid;
    }
    if (tid < TT) {
        int cnt = 0;
        for (int j = 0; j < BB; j++) cnt += (slen[j] > tid);
        g_act[tid] = cnt;
    }
}

// ---------------- pre-split X: gather emb rows, hi/lo bf16, zeros if inactive --
__global__ __launch_bounds__(256) void k_embed(const int* __restrict__ tok32,
                                               const float* __restrict__ emb)
{
    const int tid = threadIdx.x;
    const int r = blockIdx.x * 8 + (tid >> 5);   // global row = t*64 + m
    const int lane = tid & 31;
    const int t = r >> 6, m = r & 63;
    const bool act = (m < g_act[t]);
    int tok = 0;
    if (act) {
        size_t off = (size_t)g_perm[m] * TT + t;
        tok = g_is64 ? tok32[2 * off] : tok32[off];
    }
#pragma unroll
    for (int i = 0; i < 4; i++) {
        int k = i * 128 + lane * 4;
        uint2 hi = make_uint2(0u, 0u), lo = make_uint2(0u, 0u);
        if (act) {
            float4 x = *(const float4*)&emb[(size_t)tok * DD + k];
            split_pack(x.x, x.y, hi.x, lo.x);
            split_pack(x.z, x.w, hi.y, lo.y);
        }
        ((uint2*)g_xh)[(size_t)r * 128 + i * 32 + lane] = hi;
        ((uint2*)g_xl)[(size_t)r * 128 + i * 32 + lane] = lo;
    }
}

// ---------------- pre-split W_ih into bf16 hi/lo planes -------------------------
__global__ __launch_bounds__(256) void k_wsplit(const float* __restrict__ W)
{
    const int tid = threadIdx.x;
    const int r = blockIdx.x * 8 + (tid >> 5);   // row in [0, 4096)
    const int lane = tid & 31;
#pragma unroll
    for (int i = 0; i < 4; i++) {
        int k = i * 128 + lane * 4;
        float4 w = *(const float4*)&W[(size_t)r * DD + k];
        uint2 hi, lo;
        split_pack(w.x, w.y, hi.x, lo.x);
        split_pack(w.z, w.w, hi.y, lo.y);
        ((uint2*)g_wih_h)[(size_t)r * 128 + i * 32 + lane] = hi;
        ((uint2*)g_wih_l)[(size_t)r * 128 + i * 32 + lane] = lo;
    }
}

// ---------------- phase 1: dense bf16 GEMM gates_x = X @ W_ih^T + biases --------
// (unchanged from passing round-13/15 version: M32 x N32 warp tiles, ~416 us)
#define SMEM1 110592
__global__ __launch_bounds__(256, 2) void k_input_gemm(
    const float* __restrict__ b_ih,
    const float* __restrict__ b_hh)
{
    const int t = blockIdx.y;
    const int Mact = g_act[t];
    if (Mact == 0) return;
    const int n0 = blockIdx.x * 128;

    extern __shared__ char dyn1[];
    const unsigned sbase = (unsigned)__cvta_generic_to_shared(dyn1);

    const int tid = threadIdx.x, wid = tid >> 5, lane = tid & 31;
    const int mw = wid & 1, nw = wid >> 1;      // mw 0..1 (M32), nw 0..3 (N32)
    const bool f0act = (mw * 32 < Mact);
    const bool f1act = (mw * 32 + 16 < Mact);

    const int aRow = mw * 32 + (lane & 15);
    const int aCo  = (lane >> 4) << 3;
    const int bR   = nw * 32 + ((lane >> 4) << 3) + (lane & 7);
    const int bCo  = ((lane >> 3) & 1) << 3;

    float acc[2][4][4];
#pragma unroll
    for (int f = 0; f < 2; f++)
#pragma unroll
        for (int i = 0; i < 4; i++)
#pragma unroll
            for (int j = 0; j < 4; j++) acc[f][i][j] = 0.f;

    auto stage = [&](int kc, int b) {
        unsigned base = sbase + b * 55296;
#pragma unroll
        for (int v = 0; v < 4; v++) {           // A
            int e = tid + 256 * v;              // < 1024
            int plane = e >> 9, rr = (e >> 3) & 63, ch = e & 7;
            const unsigned* src = (plane ? g_xl : g_xh) +
                ((size_t)(t * 64 + rr) * 256 + kc * 32 + ch * 4);
            cp16(base + plane * 9216 + rr * 144 + ch * 16, src);
        }
#pragma unroll
        for (int v = 0; v < 8; v++) {           // W (plane stride 18432)
            int e = tid + 256 * v;              // < 2048
            int plane = e >> 10, rr = (e >> 3) & 127, ch = e & 7;
            const unsigned* src = (plane ? g_wih_l : g_wih_h) +
                ((size_t)(n0 + rr) * 256 + kc * 32 + ch * 4);
            cp16(base + 18432 + plane * 18432 + rr * 144 + ch * 16, src);
        }
    };

    stage(0, 0); cp_commit();

    for (int kc = 0; kc < 8; kc++) {            // 8 chunks of 64 k
        if (kc < 7) { stage(kc + 1, (kc + 1) & 1); cp_commit(); }
        if (kc < 7) cp_wait<1>(); else cp_wait<0>();
        __syncthreads();
        if (f0act) {
            const char* buf = dyn1 + (kc & 1) * 55296;
            const __nv_bfloat16* Ah = (const __nv_bfloat16*)(buf);
            const __nv_bfloat16* Al = (const __nv_bfloat16*)(buf + 9216);
            const __nv_bfloat16* Wh = (const __nv_bfloat16*)(buf + 18432);
            const __nv_bfloat16* Wl = (const __nv_bfloat16*)(buf + 36864);
#pragma unroll
            for (int ks = 0; ks < 4; ks++) {
                unsigned aH0[4], aL0[4], aH1[4], aL1[4];
                unsigned bH0[4], bL0[4], bH1[4], bL1[4];
                int c = ks * 16;
                ldsm4(aH0, Ah + aRow * 72 + c + aCo);
                ldsm4(aL0, Al + aRow * 72 + c + aCo);
                if (f1act) {
                    ldsm4(aH1, Ah + (aRow + 16) * 72 + c + aCo);
                    ldsm4(aL1, Al + (aRow + 16) * 72 + c + aCo);
                }
                ldsm4(bH0, Wh + bR * 72 + c + bCo);
                ldsm4(bL0, Wl + bR * 72 + c + bCo);
                ldsm4(bH1, Wh + (bR + 16) * 72 + c + bCo);
                ldsm4(bL1, Wl + (bR + 16) * 72 + c + bCo);
                mma16816(acc[0][0], aH0, bH0[0], bH0[1]);
                mma16816(acc[0][1], aH0, bH0[2], bH0[3]);
                mma16816(acc[0][2], aH0, bH1[0], bH1[1]);
                mma16816(acc[0][3], aH0, bH1[2], bH1[3]);
                mma16816(acc[0][0], aH0, bL0[0], bL0[1]);
                mma16816(acc[0][1], aH0, bL0[2], bL0[3]);
                mma16816(acc[0][2], aH0, bL1[0], bL1[1]);
                mma16816(acc[0][3], aH0, bL1[2], bL1[3]);
                mma16816(acc[0][0], aL0, bH0[0], bH0[1]);
                mma16816(acc[0][1], aL0, bH0[2], bH0[3]);
                mma16816(acc[0][2], aL0, bH1[0], bH1[1]);
                mma16816(acc[0][3], aL0, bH1[2], bH1[3]);
                if (f1act) {
                    mma16816(acc[1][0], aH1, bH0[0], bH0[1]);
                    mma16816(acc[1][1], aH1, bH0[2], bH0[3]);
                    mma16816(acc[1][2], aH1, bH1[0], bH1[1]);
                    mma16816(acc[1][3], aH1, bH1[2], bH1[3]);
                    mma16816(acc[1][0], aH1, bL0[0], bL0[1]);
                    mma16816(acc[1][1], aH1, bL0[2], bL0[3]);
                    mma16816(acc[1][2], aH1, bL1[0], bL1[1]);
                    mma16816(acc[1][3], aH1, bL1[2], bL1[3]);
                    mma16816(acc[1][0], aL1, bH0[0], bH0[1]);
                    mma16816(acc[1][1], aL1, bH0[2], bH0[3]);
                    mma16816(acc[1][2], aL1, bH1[0], bH1[1]);
                    mma16816(acc[1][3], aL1, bH1[2], bH1[3]);
                }
            }
        }
        __syncthreads();
    }

    if (!f0act) return;
    const int lr = lane >> 2;
    const int jj = 2 * (lane & 3);
    float* go = g_gates + ((size_t)t * BB) * GG;
#pragma unroll
    for (int f = 0; f < 2; f++) {
        int rbase = mw * 32 + f * 16 + lr;
#pragma unroll
        for (int nt = 0; nt < 4; nt++) {
            int col = n0 + nw * 32 + nt * 8 + jj;
            float2 b0 = *(const float2*)&b_ih[col];
            float2 b1 = *(const float2*)&b_hh[col];
            float bx = b0.x + b1.x, by = b0.y + b1.y;
            if (rbase < Mact)
                *(float2*)(go + (size_t)rbase * GG + col) =
                    make_float2(acc[f][nt][0] + bx, acc[f][nt][1] + by);
            if (rbase + 8 < Mact)
                *(float2*)(go + (size_t)(rbase + 8) * GG + col) =
                    make_float2(acc[f][nt][2] + bx, acc[f][nt][3] + by);
        }
    }
}

// ---------------- phase 2: persistent recurrent kernel -------------------------
// 128 CTAs x 512 threads (16 warps), warp map kw8 x nw2. B-hi fragments are
// STEP-INVARIANT: hoisted into registers in a prologue (8 ldsm/warp) and reused
// for all 256 steps; B-lo ldsm'd from resident WsL (1/chunk). Warp kw handles
// local k16 index kw of every 128k chunk -> all warps active every chunk.
// h staged via cp.async with the phase-1-proven TWO-sync pattern (post-compute
// sync closes the WAR window that broke r8/r9). 8-way kw partials in Gs,
// reduced with gates_x in the update.
// smem: WsL 0..66048 (resident), WsH 66048..132096 (prologue only), then
//   overlay: h buf b @ 66048+b*34816 (hi +0, lo +17408) .. 135680,
//   Gs 135680..201216 (8kw x 4gate x 64 x 8 f32), Cs ..203264,
//   act ..204288, perm ..204544
#define SMEM2 204544
__global__ __launch_bounds__(512, 1) void k_recurrent(
    const float* __restrict__ W_hh,
    float*       __restrict__ out)
{
    extern __shared__ char dyn[];
    __nv_bfloat16* WsL = (__nv_bfloat16*)(dyn);            // resident
    __nv_bfloat16* WsH = (__nv_bfloat16*)(dyn + 66048);    // prologue only
    float*         Gs  = (float*)(dyn + 135680);           // 65536 B
    float*         Cs  = (float*)(dyn + 201216);           //  2048 B
    int*         s_act = (int*)(dyn + 203264);             //  1024 B
    int*        s_perm = (int*)(dyn + 204288);             //   256 B
    __shared__ unsigned s_base;

    const unsigned sbase = (unsigned)__cvta_generic_to_shared(dyn);
    const int tid = threadIdx.x;
    const int cta = blockIdx.x;
    const int hc0 = cta * 8;
    const int wid = tid >> 5, lane = tid & 31;
    const int kw = wid >> 1, nw = wid & 1;

    if (tid < TT) s_act[tid] = g_act[tid];
    if (tid < BB) s_perm[tid] = g_perm[tid];
    if (tid == 0) s_base = *((volatile unsigned*)&g_gen);
    if (tid < BB * 8) Cs[tid] = 0.f;

    // stage W_hh slice hi/lo (rows (q>>3)*H + hc0 + (q&7), q = 0..31)
    for (int v = 0; v < 16; v++) {
        int e = tid + 512 * v;         // 8192 float4s = 32 rows x 256
        int q = e >> 8, c4 = e & 255;
        int gr = (q >> 3) * HH + hc0 + (q & 7);
        float4 w = *(const float4*)&W_hh[(size_t)gr * HH + c4 * 4];
        unsigned h0, l0, h1, l1;
        split_pack(w.x, w.y, h0, l0);
        split_pack(w.z, w.w, h1, l1);
        unsigned idx = q * 516 + c4 * 2;
        ((unsigned*)WsH)[idx]     = h0; ((unsigned*)WsH)[idx + 1] = h1;
        ((unsigned*)WsL)[idx]     = l0; ((unsigned*)WsL)[idx + 1] = l1;
    }

    // zero h parity 0 (32768 u32 per plane chip-wide = 128 CTAs x 256)
    if (tid < 256) {
        int i = cta * 256 + tid;
        ((unsigned*)g_hh[0])[i] = 0u;
        ((unsigned*)g_hl[0])[i] = 0u;
    }
    __syncthreads();   // W staged, visible

    // B-hi fragments -> registers, once for all 256 steps
    const int bRow = nw * 16 + ((lane >> 4) << 3) + (lane & 7);
    const int bCo  = ((lane >> 3) & 1) << 3;
    unsigned bHreg[8][4];
#pragma unroll
    for (int kc = 0; kc < 8; kc++)
        ldsm4(bHreg[kc], WsH + bRow * 1032 + kc * 128 + kw * 16 + bCo);
    __syncthreads();   // all warps done reading WsH before h staging reuses it

    unsigned gen = s_base;
    grid_barrier(gen);   // h zeroed + visible everywhere

    const int aLn  = lane & 15;
    const int aCo  = (lane >> 4) << 3;
    const int lr   = lane >> 2;
    const int jj   = 2 * (lane & 3);
    const int um   = tid >> 3, uj = tid & 7;   // update mapping

    for (int t = 0; t < TT; t++) {
        const int Mact = s_act[t];
        if (Mact == 0) break;            // non-increasing: uniform across CTAs
        const int p = t & 1;

        // prefetch gates_x with the UPDATE mapping (consumed after GEMM)
        float gxr[4] = {0.f, 0.f, 0.f, 0.f};
        if (um < Mact) {
            const float* gbase = g_gates + ((size_t)t * BB + um) * GG;
#pragma unroll
            for (int g = 0; g < 4; g++)
                gxr[g] = gbase[g * HH + hc0 + uj];
        }

        float acc[4][2][4];
#pragma unroll
        for (int f = 0; f < 4; f++)
#pragma unroll
            for (int n = 0; n < 2; n++)
#pragma unroll
                for (int j = 0; j < 4; j++) acc[f][n][j] = 0.f;

        const unsigned* hhu = (const unsigned*)g_hh[p];
        const unsigned* hlu = (const unsigned*)g_hl[p];

        // cp.async h staging: 2048 cp16 per 128k chunk -> 4 per thread
        //   e = tid + 512*s: plane = e>>10, rr = (e>>4)&63, c4 = e&15
        //   global u32: rr*512 + kc*64 + c4*4
        //   smem: 66048 + b*34816 + plane*17408 + rr*272 + c4*16
        auto stageh = [&](int kc, int b) {
            unsigned base = sbase + 66048 + b * 34816;
#pragma unroll
            for (int s = 0; s < 4; s++) {
                int e = tid + 512 * s;
                int plane = e >> 10, rr = (e >> 4) & 63, c4 = e & 15;
                const unsigned* src = (plane ? hlu : hhu) +
                    (rr * 512 + kc * 64 + c4 * 4);
                cp16(base + plane * 17408 + rr * 272 + c4 * 16, src);
            }
        };

        stageh(0, 0); cp_commit();

#pragma unroll
        for (int kc = 0; kc < 8; kc++) {       // 8 chunks of 128 k
            if (kc < 7) { stageh(kc + 1, (kc + 1) & 1); cp_commit(); }
            if (kc < 7) cp_wait<1>(); else cp_wait<0>();
            __syncthreads();
            {
                const char* buf = dyn + 66048 + (kc & 1) * 34816;
                const __nv_bfloat16* AhH = (const __nv_bfloat16*)(buf);
                const __nv_bfloat16* AhL = (const __nv_bfloat16*)(buf + 17408);
                unsigned bL[4];
                ldsm4(bL, WsL + bRow * 1032 + kc * 128 + kw * 16 + bCo);
                int ac = kw * 16 + aCo;
#pragma unroll
                for (int f = 0; f < 4; f++) {
                    if (f * 16 < Mact) {
                        unsigned aH[4], aL[4];
                        ldsm4(aH, AhH + (f * 16 + aLn) * 136 + ac);
                        ldsm4(aL, AhL + (f * 16 + aLn) * 136 + ac);
                        mma16816(acc[f][0], aH, bHreg[kc][0], bHreg[kc][1]);
                        mma16816(acc[f][1], aH, bHreg[kc][2], bHreg[kc][3]);
                        mma16816(acc[f][0], aH, bL[0], bL[1]);
                        mma16816(acc[f][1], aH, bL[2], bL[3]);
                        mma16816(acc[f][0], aL, bHreg[kc][0], bHreg[kc][1]);
                        mma16816(acc[f][1], aL, bHreg[kc][2], bHreg[kc][3]);
                    }
                }
            }
            __syncthreads();   // post-compute WAR guard (the r8/r9 fix)
        }

        // kw partial sums -> Gs[kw] (gx added in the update)
#pragma unroll
        for (int f = 0; f < 4; f++) {
            if (f * 16 < Mact) {
                int m0 = f * 16 + lr;
#pragma unroll
                for (int nt = 0; nt < 2; nt++) {
                    int gate = nw * 2 + nt;
                    float* gp = Gs + ((kw * 4 + gate) * 64) * 8;
                    if (m0 < Mact) {
                        gp[m0 * 8 + jj]     = acc[f][nt][0];
                        gp[m0 * 8 + jj + 1] = acc[f][nt][1];
                    }
                    if (m0 + 8 < Mact) {
                        gp[(m0 + 8) * 8 + jj]     = acc[f][nt][2];
                        gp[(m0 + 8) * 8 + jj + 1] = acc[f][nt][3];
                    }
                }
            }
        }
        __syncthreads();

        // CTA-local LSTM update; sum 8 kw partials + gates_x; write next parity
        const int pn = p ^ 1;
        if (tid < Mact * 8) {
            int m = um, j = uj;
            float gsum[4];
#pragma unroll
            for (int g = 0; g < 4; g++) gsum[g] = gxr[g];
#pragma unroll
            for (int k = 0; k < 8; k++)
#pragma unroll
                for (int g = 0; g < 4; g++)
                    gsum[g] += Gs[((k * 4 + g) * 64 + m) * 8 + j];
            float is = 1.f / (1.f + expf(-gsum[0]));
            float fs = 1.f / (1.f + expf(-gsum[1]));
            float gt = tanhf(gsum[2]);
            float os = 1.f / (1.f + expf(-gsum[3]));
            float cn = fs * Cs[tid] + is * gt;
            Cs[tid] = cn;
            float hn = os * tanhf(cn);
            int col = hc0 + j;
            g_hout[(size_t)m * HH + col] = hn;
            __nv_bfloat16 hh = __float2bfloat16(hn);
            g_hh[pn][m * HH + col] = hh;
            g_hl[pn][m * HH + col] = __float2bfloat16(hn - __bfloat162float(hh));
        }
        grid_barrier(gen);
    }

    // scatter back to original batch order (CTA-owned cols only)
    if (tid < BB * 8) {
        int m = tid >> 3, j = tid & 7;
        out[(size_t)s_perm[m] * HH + hc0 + j] = g_hout[(size_t)m * HH + hc0 + j];
    }
}

// ---------------- launch --------------------------------------------------------
extern "C" void kernel_launch(void* const* d_in, const int* in_sizes, int n_in,
                              void* d_out, int out_size)
{
    const int*   tokens  = (const int*)  d_in[0];  // int32/int64 autodetected
    const int*   lengths = (const int*)  d_in[1];
    const float* emb     = (const float*)d_in[2];
    const float* W_ih    = (const float*)d_in[3];
    const float* W_hh    = (const float*)d_in[4];
    const float* b_ih    = (const float*)d_in[5];
    const float* b_hh    = (const float*)d_in[6];
    float* out = (float*)d_out;

    cudaFuncSetAttribute(k_input_gemm,
                         cudaFuncAttributeMaxDynamicSharedMemorySize, SMEM1);
    cudaFuncSetAttribute(k_recurrent,
                         cudaFuncAttributeMaxDynamicSharedMemorySize, SMEM2);

    k_prep<<<1, 256>>>(lengths);
    k_wsplit<<<GG / 8, 256>>>(W_ih);                 // 512 CTAs
    k_embed<<<TT * BB / 8, 256>>>(tokens, emb);      // 2048 CTAs

    dim3 g1(GG / 128, TT);                           // (32, 256)
    k_input_gemm<<<g1, 256, SMEM1>>>(b_ih, b_hh);

    k_recurrent<<<NCTA2, 512, SMEM2>>>(W_hh, out);
}

// round 17
// speedup vs baseline: 1.1987x; 1.1987x over previous
#include <cuda_runtime.h>
#include <cuda_bf16.h>
#include <cstdint>
#include <math.h>

// Problem constants
#define BB   64
#define TT   256
#define DD   512
#define HH   1024
#define GG   4096   // 4*H
#define NCTA2 128   // persistent recurrent kernel grid size

// ---------------- device scratch (static; no cudaMalloc allowed) --------------
__device__ float    g_gates[(size_t)TT * BB * GG];          // x@W_ih^T + biases
__device__ __align__(16) unsigned g_xh[(size_t)TT * BB * (DD/2)];  // X hi plane (u32 = 2 bf16)
__device__ __align__(16) unsigned g_xl[(size_t)TT * BB * (DD/2)];  // X lo plane
__device__ __align__(16) unsigned g_wih_h[GG * (DD/2)];     // W_ih hi plane
__device__ __align__(16) unsigned g_wih_l[GG * (DD/2)];     // W_ih lo plane
__device__ __align__(16) __nv_bfloat16 g_hh[2][BB * HH];    // h hi, double buffered
__device__ __align__(16) __nv_bfloat16 g_hl[2][BB * HH];    // h lo
__device__ float    g_hout[BB * HH];                        // last-active h (fp32)
__device__ int      g_perm[BB];
__device__ int      g_act[TT];
__device__ int      g_is64;
__device__ unsigned g_cnt8[8 * 64];                         // sub-counters, 256B apart
__device__ unsigned g_cnt = 0;                              // master counter
__device__ unsigned g_gen = 0;                              // barrier generation

// ---------------- small asm helpers --------------------------------------------
__device__ __forceinline__ void cp16(unsigned saddr, const void* g) {
    asm volatile("cp.async.cg.shared.global [%0], [%1], 16;"
                 :: "r"(saddr), "l"(g) : "memory");
}
__device__ __forceinline__ void cp_commit() {
    asm volatile("cp.async.commit_group;" ::: "memory");
}
template<int N> __device__ __forceinline__ void cp_wait() {
    asm volatile("cp.async.wait_group %0;" :: "n"(N) : "memory");
}
__device__ __forceinline__ uint4 ldcg4(const unsigned* p) {
    uint4 v;
    asm volatile("ld.global.cg.v4.u32 {%0,%1,%2,%3}, [%4];"
                 : "=r"(v.x), "=r"(v.y), "=r"(v.z), "=r"(v.w) : "l"(p) : "memory");
    return v;
}
__device__ __forceinline__ void ldsm4(unsigned* r, const __nv_bfloat16* p) {
    unsigned a = (unsigned)__cvta_generic_to_shared((void*)p);
    asm volatile("ldmatrix.sync.aligned.m8n8.x4.shared.b16 {%0,%1,%2,%3}, [%4];"
                 : "=r"(r[0]), "=r"(r[1]), "=r"(r[2]), "=r"(r[3]) : "r"(a));
}
__device__ __forceinline__ void mma16816(float* c, const unsigned* a,
                                         unsigned b0, unsigned b1) {
    asm volatile("mma.sync.aligned.m16n8k16.row.col.f32.bf16.bf16.f32 "
                 "{%0,%1,%2,%3},{%4,%5,%6,%7},{%8,%9},{%0,%1,%2,%3};"
                 : "+f"(c[0]), "+f"(c[1]), "+f"(c[2]), "+f"(c[3])
                 : "r"(a[0]), "r"(a[1]), "r"(a[2]), "r"(a[3]), "r"(b0), "r"(b1));
}

// ---------------- bf16 hi/lo split + pack --------------------------------------
__device__ __forceinline__ unsigned packbf(__nv_bfloat16 a, __nv_bfloat16 b) {
    return ((unsigned)__bfloat16_as_ushort(b) << 16) | (unsigned)__bfloat16_as_ushort(a);
}
__device__ __forceinline__ void split_pack(float x, float y, unsigned& hi, unsigned& lo) {
    __nv_bfloat16 hx = __float2bfloat16(x);
    __nv_bfloat16 hy = __float2bfloat16(y);
    hi = packbf(hx, hy);
    lo = packbf(__float2bfloat16(x - __bfloat162float(hx)),
                __float2bfloat16(y - __bfloat162float(hy)));
}

// ---------------- grid barrier (monotone generation, TREE counters) ------------
__device__ __forceinline__ void grid_barrier(unsigned& gen)
{
    __syncthreads();
    gen++;
    if (threadIdx.x == 0) {
        __threadfence();
        int grp = blockIdx.x & 7;
        unsigned prev = atomicAdd(&g_cnt8[grp * 64], 1u);
        bool released = false;
        if (prev == 15u) {                       // last of this 16-CTA group
            atomicExch(&g_cnt8[grp * 64], 0u);   // reset before master arrive
            unsigned p2 = atomicAdd(&g_cnt, 1u);
            if (p2 == 7u) {                      // last group
                atomicExch(&g_cnt, 0u);
                __threadfence();
                atomicExch(&g_gen, gen);
                released = true;
            }
        }
        if (!released) {
            while (*((volatile unsigned*)&g_gen) < gen) { }
            __threadfence();
        }
    }
    __syncthreads();
}

// ---------------- prep: parallel rank sort by length (desc, stable) ------------
__global__ void k_prep(const int* __restrict__ len32)
{
    __shared__ int slen[BB];
    const int tid = threadIdx.x;
    const int is64 = (len32[1] == 0) ? 1 : 0;   // lengths >= 1 always
    if (tid == 0) g_is64 = is64;
    if (tid < BB) slen[tid] = is64 ? len32[2 * tid] : len32[tid];
    __syncthreads();
    if (tid < BB) {
        int li = slen[tid], r = 0;
        for (int j = 0; j < BB; j++) {
            int lj = slen[j];
            r += (lj > li) || (lj == li && j < tid);
        }
        g_perm[r] = tid;
    }
    if (tid < TT) {
        int cnt = 0;
        for (int j = 0; j < BB; j++) cnt += (slen[j] > tid);
        g_act[tid] = cnt;
    }
}

// ---------------- pre-split X: gather emb rows, hi/lo bf16, zeros if inactive --
__global__ __launch_bounds__(256) void k_embed(const int* __restrict__ tok32,
                                               const float* __restrict__ emb)
{
    const int tid = threadIdx.x;
    const int r = blockIdx.x * 8 + (tid >> 5);   // global row = t*64 + m
    const int lane = tid & 31;
    const int t = r >> 6, m = r & 63;
    const bool act = (m < g_act[t]);
    int tok = 0;
    if (act) {
        size_t off = (size_t)g_perm[m] * TT + t;
        tok = g_is64 ? tok32[2 * off] : tok32[off];
    }
#pragma unroll
    for (int i = 0; i < 4; i++) {
        int k = i * 128 + lane * 4;
        uint2 hi = make_uint2(0u, 0u), lo = make_uint2(0u, 0u);
        if (act) {
            float4 x = *(const float4*)&emb[(size_t)tok * DD + k];
            split_pack(x.x, x.y, hi.x, lo.x);
            split_pack(x.z, x.w, hi.y, lo.y);
        }
        ((uint2*)g_xh)[(size_t)r * 128 + i * 32 + lane] = hi;
        ((uint2*)g_xl)[(size_t)r * 128 + i * 32 + lane] = lo;
    }
}

// ---------------- pre-split W_ih into bf16 hi/lo planes -------------------------
__global__ __launch_bounds__(256) void k_wsplit(const float* __restrict__ W)
{
    const int tid = threadIdx.x;
    const int r = blockIdx.x * 8 + (tid >> 5);   // row in [0, 4096)
    const int lane = tid & 31;
#pragma unroll
    for (int i = 0; i < 4; i++) {
        int k = i * 128 + lane * 4;
        float4 w = *(const float4*)&W[(size_t)r * DD + k];
        uint2 hi, lo;
        split_pack(w.x, w.y, hi.x, lo.x);
        split_pack(w.z, w.w, hi.y, lo.y);
        ((uint2*)g_wih_h)[(size_t)r * 128 + i * 32 + lane] = hi;
        ((uint2*)g_wih_l)[(size_t)r * 128 + i * 32 + lane] = lo;
    }
}

// ---------------- phase 1: dense bf16 GEMM gates_x = X @ W_ih^T + biases --------
// (unchanged from passing round-13/15 version: M32 x N32 warp tiles, ~416 us)
#define SMEM1 110592
__global__ __launch_bounds__(256, 2) void k_input_gemm(
    const float* __restrict__ b_ih,
    const float* __restrict__ b_hh)
{
    const int t = blockIdx.y;
    const int Mact = g_act[t];
    if (Mact == 0) return;
    const int n0 = blockIdx.x * 128;

    extern __shared__ char dyn1[];
    const unsigned sbase = (unsigned)__cvta_generic_to_shared(dyn1);

    const int tid = threadIdx.x, wid = tid >> 5, lane = tid & 31;
    const int mw = wid & 1, nw = wid >> 1;      // mw 0..1 (M32), nw 0..3 (N32)
    const bool f0act = (mw * 32 < Mact);
    const bool f1act = (mw * 32 + 16 < Mact);

    const int aRow = mw * 32 + (lane & 15);
    const int aCo  = (lane >> 4) << 3;
    const int bR   = nw * 32 + ((lane >> 4) << 3) + (lane & 7);
    const int bCo  = ((lane >> 3) & 1) << 3;

    float acc[2][4][4];
#pragma unroll
    for (int f = 0; f < 2; f++)
#pragma unroll
        for (int i = 0; i < 4; i++)
#pragma unroll
            for (int j = 0; j < 4; j++) acc[f][i][j] = 0.f;

    auto stage = [&](int kc, int b) {
        unsigned base = sbase + b * 55296;
#pragma unroll
        for (int v = 0; v < 4; v++) {           // A
            int e = tid + 256 * v;              // < 1024
            int plane = e >> 9, rr = (e >> 3) & 63, ch = e & 7;
            const unsigned* src = (plane ? g_xl : g_xh) +
                ((size_t)(t * 64 + rr) * 256 + kc * 32 + ch * 4);
            cp16(base + plane * 9216 + rr * 144 + ch * 16, src);
        }
#pragma unroll
        for (int v = 0; v < 8; v++) {           // W (plane stride 18432)
            int e = tid + 256 * v;              // < 2048
            int plane = e >> 10, rr = (e >> 3) & 127, ch = e & 7;
            const unsigned* src = (plane ? g_wih_l : g_wih_h) +
                ((size_t)(n0 + rr) * 256 + kc * 32 + ch * 4);
            cp16(base + 18432 + plane * 18432 + rr * 144 + ch * 16, src);
        }
    };

    stage(0, 0); cp_commit();

    for (int kc = 0; kc < 8; kc++) {            // 8 chunks of 64 k
        if (kc < 7) { stage(kc + 1, (kc + 1) & 1); cp_commit(); }
        if (kc < 7) cp_wait<1>(); else cp_wait<0>();
        __syncthreads();
        if (f0act) {
            const char* buf = dyn1 + (kc & 1) * 55296;
            const __nv_bfloat16* Ah = (const __nv_bfloat16*)(buf);
            const __nv_bfloat16* Al = (const __nv_bfloat16*)(buf + 9216);
            const __nv_bfloat16* Wh = (const __nv_bfloat16*)(buf + 18432);
            const __nv_bfloat16* Wl = (const __nv_bfloat16*)(buf + 36864);
#pragma unroll
            for (int ks = 0; ks < 4; ks++) {
                unsigned aH0[4], aL0[4], aH1[4], aL1[4];
                unsigned bH0[4], bL0[4], bH1[4], bL1[4];
                int c = ks * 16;
                ldsm4(aH0, Ah + aRow * 72 + c + aCo);
                ldsm4(aL0, Al + aRow * 72 + c + aCo);
                if (f1act) {
                    ldsm4(aH1, Ah + (aRow + 16) * 72 + c + aCo);
                    ldsm4(aL1, Al + (aRow + 16) * 72 + c + aCo);
                }
                ldsm4(bH0, Wh + bR * 72 + c + bCo);
                ldsm4(bL0, Wl + bR * 72 + c + bCo);
                ldsm4(bH1, Wh + (bR + 16) * 72 + c + bCo);
                ldsm4(bL1, Wl + (bR + 16) * 72 + c + bCo);
                mma16816(acc[0][0], aH0, bH0[0], bH0[1]);
                mma16816(acc[0][1], aH0, bH0[2], bH0[3]);
                mma16816(acc[0][2], aH0, bH1[0], bH1[1]);
                mma16816(acc[0][3], aH0, bH1[2], bH1[3]);
                mma16816(acc[0][0], aH0, bL0[0], bL0[1]);
                mma16816(acc[0][1], aH0, bL0[2], bL0[3]);
                mma16816(acc[0][2], aH0, bL1[0], bL1[1]);
                mma16816(acc[0][3], aH0, bL1[2], bL1[3]);
                mma16816(acc[0][0], aL0, bH0[0], bH0[1]);
                mma16816(acc[0][1], aL0, bH0[2], bH0[3]);
                mma16816(acc[0][2], aL0, bH1[0], bH1[1]);
                mma16816(acc[0][3], aL0, bH1[2], bH1[3]);
                if (f1act) {
                    mma16816(acc[1][0], aH1, bH0[0], bH0[1]);
                    mma16816(acc[1][1], aH1, bH0[2], bH0[3]);
                    mma16816(acc[1][2], aH1, bH1[0], bH1[1]);
                    mma16816(acc[1][3], aH1, bH1[2], bH1[3]);
                    mma16816(acc[1][0], aH1, bL0[0], bL0[1]);
                    mma16816(acc[1][1], aH1, bL0[2], bL0[3]);
                    mma16816(acc[1][2], aH1, bL1[0], bL1[1]);
                    mma16816(acc[1][3], aH1, bL1[2], bL1[3]);
                    mma16816(acc[1][0], aL1, bH0[0], bH0[1]);
                    mma16816(acc[1][1], aL1, bH0[2], bH0[3]);
                    mma16816(acc[1][2], aL1, bH1[0], bH1[1]);
                    mma16816(acc[1][3], aL1, bH1[2], bH1[3]);
                }
            }
        }
        __syncthreads();
    }

    if (!f0act) return;
    const int lr = lane >> 2;
    const int jj = 2 * (lane & 3);
    float* go = g_gates + ((size_t)t * BB) * GG;
#pragma unroll
    for (int f = 0; f < 2; f++) {
        int rbase = mw * 32 + f * 16 + lr;
#pragma unroll
        for (int nt = 0; nt < 4; nt++) {
            int col = n0 + nw * 32 + nt * 8 + jj;
            float2 b0 = *(const float2*)&b_ih[col];
            float2 b1 = *(const float2*)&b_hh[col];
            float bx = b0.x + b1.x, by = b0.y + b1.y;
            if (rbase < Mact)
                *(float2*)(go + (size_t)rbase * GG + col) =
                    make_float2(acc[f][nt][0] + bx, acc[f][nt][1] + by);
            if (rbase + 8 < Mact)
                *(float2*)(go + (size_t)(rbase + 8) * GG + col) =
                    make_float2(acc[f][nt][2] + bx, acc[f][nt][3] + by);
        }
    }
}

// ---------------- phase 2: persistent recurrent kernel -------------------------
// 128 CTAs x 512 threads (16 warps). Warp map kw4 x mw4: each warp owns
// M16 x N32 x (2 k16 slices per chunk) -> A frags read exactly once chip-wide,
// B duplicated only across mw. ldsm/chunk: 12/warp (49 KB vs r15's 128 KB).
// acc = 16 floats (low regs). 4-way kw partials in Gs (32 KB), OVERLAID on
// h buffer 0 (dead at epilogue: last chunk reads buf1; all buf0 readers done
// by the kc=7 sync). Staging / 1-sync-per-chunk skeleton / barrier = r15.
// smem: WsH 0..66048, WsL ..132096, h buf b @132096+b*34816 (hi +0, lo +17408)
//       ..201728; Gs = 132096..164864 (overlay of buf0);
//       Cs 201728..203776, act ..204800, perm ..205056
#define SMEM2 205056
__global__ __launch_bounds__(512, 1) void k_recurrent(
    const float* __restrict__ W_hh,
    float*       __restrict__ out)
{
    extern __shared__ char dyn[];
    __nv_bfloat16* WsH = (__nv_bfloat16*)(dyn);            //  66048 B (32 x 1032)
    __nv_bfloat16* WsL = (__nv_bfloat16*)(dyn + 66048);    //  66048 B
    float*         Gs  = (float*)(dyn + 132096);           //  32768 B (overlay buf0)
    float*         Cs  = (float*)(dyn + 201728);           //   2048 B (64 x 8)
    int*         s_act = (int*)(dyn + 203776);             //   1024 B
    int*        s_perm = (int*)(dyn + 204800);             //    256 B
    __shared__ unsigned s_base;

    const int tid = threadIdx.x;
    const int cta = blockIdx.x;
    const int hc0 = cta * 8;
    const int wid = tid >> 5, lane = tid & 31;
    const int kw = wid & 3, mw = wid >> 2;

    if (tid < TT) s_act[tid] = g_act[tid];
    if (tid < BB) s_perm[tid] = g_perm[tid];
    if (tid == 0) s_base = *((volatile unsigned*)&g_gen);
    if (tid < BB * 8) Cs[tid] = 0.f;

    // stage W_hh slice hi/lo (rows (q>>3)*H + hc0 + (q&7), q = 0..31)
    for (int v = 0; v < 16; v++) {
        int e = tid + 512 * v;         // 8192 float4s = 32 rows x 256
        int q = e >> 8, c4 = e & 255;
        int gr = (q >> 3) * HH + hc0 + (q & 7);
        float4 w = *(const float4*)&W_hh[(size_t)gr * HH + c4 * 4];
        unsigned h0, l0, h1, l1;
        split_pack(w.x, w.y, h0, l0);
        split_pack(w.z, w.w, h1, l1);
        unsigned idx = q * 516 + c4 * 2;
        ((unsigned*)WsH)[idx]     = h0; ((unsigned*)WsH)[idx + 1] = h1;
        ((unsigned*)WsL)[idx]     = l0; ((unsigned*)WsL)[idx + 1] = l1;
    }

    // zero h parity 0 (32768 u32 per plane chip-wide = 128 CTAs x 256)
    if (tid < 256) {
        int i = cta * 256 + tid;
        ((unsigned*)g_hh[0])[i] = 0u;
        ((unsigned*)g_hl[0])[i] = 0u;
    }
    __syncthreads();
    unsigned gen = s_base;
    grid_barrier(gen);   // h zeroed + W staged, visible everywhere

    const int aRow = mw * 16 + (lane & 15);
    const int aCo  = (lane >> 4) << 3;
    const int bRow = ((lane >> 4) << 3) + (lane & 7);   // n rows 0..15
    const int bCo  = ((lane >> 3) & 1) << 3;
    const int lr   = lane >> 2;
    const int jj   = 2 * (lane & 3);

    // staging slots: 2048 uint4 per 128k chunk -> 4 per thread at 512 threads
    //   e = tid + 512*s: plane = e>>10, rr = (e>>4)&63, c4 = e&15
    //   global uint4 idx: rr*128 + kc*16 + c4
    //   smem byte: 132096 + b*34816 + plane*17408 + rr*272 + c4*16
    int s_plane[4], s_rr[4], s_c4[4];
#pragma unroll
    for (int s = 0; s < 4; s++) {
        int e = tid + 512 * s;
        s_plane[s] = e >> 10; s_rr[s] = (e >> 4) & 63; s_c4[s] = e & 15;
    }
    const int um = tid >> 3, uj = tid & 7;    // update mapping (512 = 64*8)

    for (int t = 0; t < TT; t++) {
        const int Mact = s_act[t];
        if (Mact == 0) break;            // non-increasing: uniform across CTAs
        const int p = t & 1;
        const bool wact = (mw * 16 < Mact);

        // prefetch gates_x with the UPDATE mapping (consumed after GEMM)
        float gxr[4] = {0.f, 0.f, 0.f, 0.f};
        if (um < Mact) {
            const float* gbase = g_gates + ((size_t)t * BB + um) * GG;
#pragma unroll
            for (int g = 0; g < 4; g++)
                gxr[g] = gbase[g * HH + hc0 + uj];
        }

        float acc[4][4];
#pragma unroll
        for (int n = 0; n < 4; n++)
#pragma unroll
            for (int j = 0; j < 4; j++) acc[n][j] = 0.f;

        const uint4* hh4 = (const uint4*)g_hh[p];
        const uint4* hl4 = (const uint4*)g_hl[p];

        uint4 ra[4], rb[4];
        // load chunk 0 into ra
#pragma unroll
        for (int s = 0; s < 4; s++) {
            ra[s] = (s_rr[s] < Mact)
                ? ldcg4((const unsigned*)((s_plane[s] ? hl4 : hh4) +
                                          (s_rr[s] * 128 + s_c4[s])))
                : make_uint4(0u, 0u, 0u, 0u);
        }

#pragma unroll
        for (int kc = 0; kc < 8; kc++) {       // 8 chunks of 128 k
            uint4* cur = (kc & 1) ? rb : ra;
            uint4* nxt = (kc & 1) ? ra : rb;
            if (kc < 7) {                      // issue loads for kc+1 (overlap)
#pragma unroll
                for (int s = 0; s < 4; s++) {
                    nxt[s] = (s_rr[s] < Mact)
                        ? ldcg4((const unsigned*)((s_plane[s] ? hl4 : hh4) +
                                 (s_rr[s] * 128 + (kc + 1) * 16 + s_c4[s])))
                        : make_uint4(0u, 0u, 0u, 0u);
                }
            }
            // STS chunk kc into buffer kc&1 (WAR safe: sync in iter kc-1
            // guarantees all warps finished reading this buffer at kc-2)
            {
                char* bufw = dyn + 132096 + (kc & 1) * 34816;
#pragma unroll
                for (int s = 0; s < 4; s++) {
                    *(uint4*)(bufw + s_plane[s] * 17408 + s_rr[s] * 272 +
                              s_c4[s] * 16) = cur[s];
                }
            }
            __syncthreads();
            if (wact) {
                const char* buf = dyn + 132096 + (kc & 1) * 34816;
                const __nv_bfloat16* AhH = (const __nv_bfloat16*)(buf);
                const __nv_bfloat16* AhL = (const __nv_bfloat16*)(buf + 17408);
#pragma unroll
                for (int s = 0; s < 2; s++) {
                    int kidx = kw * 2 + s;     // this warp's k16 slices
                    unsigned aH[4], aL[4], bH0[4], bH1[4], bL0[4], bL1[4];
                    int ac = kidx * 16 + aCo;
                    int wc = kc * 128 + kidx * 16 + bCo;
                    ldsm4(aH, AhH + aRow * 136 + ac);
                    ldsm4(aL, AhL + aRow * 136 + ac);
                    ldsm4(bH0, WsH + bRow * 1032 + wc);
                    ldsm4(bH1, WsH + (bRow + 16) * 1032 + wc);
                    ldsm4(bL0, WsL + bRow * 1032 + wc);
                    ldsm4(bL1, WsL + (bRow + 16) * 1032 + wc);
                    // 4 independent acc quads, 3 mma each
                    mma16816(acc[0], aH, bH0[0], bH0[1]);
                    mma16816(acc[1], aH, bH0[2], bH0[3]);
                    mma16816(acc[2], aH, bH1[0], bH1[1]);
                    mma16816(acc[3], aH, bH1[2], bH1[3]);
                    mma16816(acc[0], aH, bL0[0], bL0[1]);
                    mma16816(acc[1], aH, bL0[2], bL0[3]);
                    mma16816(acc[2], aH, bL1[0], bL1[1]);
                    mma16816(acc[3], aH, bL1[2], bL1[3]);
                    mma16816(acc[0], aL, bH0[0], bH0[1]);
                    mma16816(acc[1], aL, bH0[2], bH0[3]);
                    mma16816(acc[2], aL, bH1[0], bH1[1]);
                    mma16816(acc[3], aL, bH1[2], bH1[3]);
                }
            }
        }

        // kw partial sums -> Gs[kw] (nt = gate; gx added in the update).
        // Gs overlays buf0: safe — all buf0 readers (compute kc=6) finished
        // before the kc=7 sync; lagging warps read buf1 only.
        if (wact) {
            int m0 = mw * 16 + lr;
#pragma unroll
            for (int nt = 0; nt < 4; nt++) {
                float* gp = Gs + ((kw * 4 + nt) * 64) * 8;
                if (m0 < Mact) {
                    gp[m0 * 8 + jj]     = acc[nt][0];
                    gp[m0 * 8 + jj + 1] = acc[nt][1];
                }
                if (m0 + 8 < Mact) {
                    gp[(m0 + 8) * 8 + jj]     = acc[nt][2];
                    gp[(m0 + 8) * 8 + jj + 1] = acc[nt][3];
                }
            }
        }
        __syncthreads();

        // CTA-local LSTM update; sum 4 kw partials + gates_x; write next parity
        const int pn = p ^ 1;
        if (tid < Mact * 8) {
            int m = um, j = uj;
            float gsum[4];
#pragma unroll
            for (int g = 0; g < 4; g++) gsum[g] = gxr[g];
#pragma unroll
            for (int k = 0; k < 4; k++)
#pragma unroll
                for (int g = 0; g < 4; g++)
                    gsum[g] += Gs[((k * 4 + g) * 64 + m) * 8 + j];
            float is = 1.f / (1.f + expf(-gsum[0]));
            float fs = 1.f / (1.f + expf(-gsum[1]));
            float gt = tanhf(gsum[2]);
            float os = 1.f / (1.f + expf(-gsum[3]));
            float cn = fs * Cs[tid] + is * gt;
            Cs[tid] = cn;
            float hn = os * tanhf(cn);
            int col = hc0 + j;
            g_hout[(size_t)m * HH + col] = hn;
            __nv_bfloat16 hh = __float2bfloat16(hn);
            g_hh[pn][m * HH + col] = hh;
            g_hl[pn][m * HH + col] = __float2bfloat16(hn - __bfloat162float(hh));
        }
        grid_barrier(gen);
    }

    // scatter back to original batch order (CTA-owned cols only)
    if (tid < BB * 8) {
        int m = tid >> 3, j = tid & 7;
        out[(size_t)s_perm[m] * HH + hc0 + j] = g_hout[(size_t)m * HH + hc0 + j];
    }
}

// ---------------- launch --------------------------------------------------------
extern "C" void kernel_launch(void* const* d_in, const int* in_sizes, int n_in,
                              void* d_out, int out_size)
{
    const int*   tokens  = (const int*)  d_in[0];  // int32/int64 autodetected
    const int*   lengths = (const int*)  d_in[1];
    const float* emb     = (const float*)d_in[2];
    const float* W_ih    = (const float*)d_in[3];
    const float* W_hh    = (const float*)d_in[4];
    const float* b_ih    = (const float*)d_in[5];
    const float* b_hh    = (const float*)d_in[6];
    float* out = (float*)d_out;

    cudaFuncSetAttribute(k_input_gemm,
                         cudaFuncAttributeMaxDynamicSharedMemorySize, SMEM1);
    cudaFuncSetAttribute(k_recurrent,
                         cudaFuncAttributeMaxDynamicSharedMemorySize, SMEM2);

    k_prep<<<1, 256>>>(lengths);
    k_wsplit<<<GG / 8, 256>>>(W_ih);                 // 512 CTAs
    k_embed<<<TT * BB / 8, 256>>>(tokens, emb);      // 2048 CTAs

    dim3 g1(GG / 128, TT);                           // (32, 256)
    k_input_gemm<<<g1, 256, SMEM1>>>(b_ih, b_hh);

    k_recurrent<<<NCTA2, 512, SMEM2>>>(W_hh, out);
}